// round 16
// baseline (speedup 1.0000x reference)
#include <cuda_runtime.h>
#include <math.h>

#define BB 8
#define TT 200
#define UU 50
#define VV 1024

#define FRONT 96
#define RW    300                  // 96 front + 200 data + 4 back; lane stride 297 = 9 mod 32 -> conflict-free
#define E0    (UU * RW)            // 15000: emit rows base
#define D0    (E0 + 49 * RW)       // 29700: dummy (all-SENT) row base
#define PADSZ 30000                // 100 rows * 300, multiple of 4
#define MITER 116                  // last capture: slot B col 49 (k=17) block t1=198 -> m=116

#define INV_LN2 1.4426950408889634f
#define LN2     0.6931471805599453f
#define NEG_INF __int_as_float(0xff800000)
#define SENT    (-1.0e30f)

__device__ __forceinline__ float ex2f(float x) {
    float r; asm("ex2.approx.f32 %0, %1;" : "=f"(r) : "f"(x)); return r;
}
__device__ __forceinline__ float lg2f(float x) {
    float r; asm("lg2.approx.f32 %0, %1;" : "=f"(r) : "f"(x)); return r;
}

// Padded per-batch scratch, log2-domain normalized log-probs, final smem layout:
// rows 0..49 blank[u] (data at FRONT+t), rows 50..98 emit[u], row 99 dummy.
__device__ float g_pad[BB * PADSZ];

// ---------------------------------------------------------------------------
// Phase 1: one block per (b,u); warp 0 = blank col (v=0), warp 1 = emit col.
// Writes (h - lse)/ln2 into padded rows; pads = SENT; pokes the DP seed.
// ---------------------------------------------------------------------------
__global__ void __launch_bounds__(64)
lse_gather_kernel(const float* __restrict__ h,
                  const int* __restrict__ targets,
                  float* __restrict__ out) {
    int bu = blockIdx.x;
    int b = bu / UU, u = bu % UU;
    int w = threadIdx.x >> 5, lane = threadIdx.x & 31;

    if (bu == 0 && threadIdx.x == 0) *out = 0.0f;   // phase 2 runs after in-stream

    float* batch = g_pad + b * PADSZ;

    if (w == 1 && u >= UU - 1) {
        float* dr = batch + D0;                     // dummy row: all SENT
        for (int i = lane; i < RW; i += 32) dr[i] = SENT;
        return;
    }

    int v = (w == 1) ? targets[b * (UU - 1) + u] : 0;
    float* row = batch + ((w == 0) ? u * RW : E0 + u * RW);

    // pads (front 96, back 4)
#pragma unroll
    for (int i = lane; i < FRONT; i += 32) row[i] = SENT;
    if (lane < RW - (FRONT + TT)) row[FRONT + TT + lane] = SENT;
    // DP seed: lane-0/slot-A activation reads blank[0][FRONT-1]; 0 here makes
    // alpha[0][0] = 0 fall out of the general recurrence.
    if (w == 0 && u == 0 && lane == 0) row[FRONT - 1] = 0.0f;

    const float* base = h + (size_t)b * TT * UU * VV + (size_t)u * VV + v;

    float x[7];
#pragma unroll
    for (int i = 0; i < 7; ++i) {
        int t = lane + 32 * i;
        x[i] = (t < TT) ? base[(size_t)t * (UU * VV)] * INV_LN2 : NEG_INF;
    }

    float m = x[0];
#pragma unroll
    for (int i = 1; i < 7; ++i) m = fmaxf(m, x[i]);
#pragma unroll
    for (int o = 16; o > 0; o >>= 1) m = fmaxf(m, __shfl_xor_sync(0xffffffffu, m, o));

    float s = 0.0f;
#pragma unroll
    for (int i = 0; i < 7; ++i) s += ex2f(x[i] - m);
#pragma unroll
    for (int o = 16; o > 0; o >>= 1) s += __shfl_xor_sync(0xffffffffu, s, o);

    float lse = m + lg2f(s);

#pragma unroll
    for (int i = 0; i < 7; ++i) {
        int t = lane + 32 * i;
        if (t < TT) row[FRONT + t] = x[i] - lse;
    }
}

// ---------------------------------------------------------------------------
// Phase 2: flat stage + fused-3 wavefront DP (direct extension of the R8
// fused-2 kernel that passed). Lane k owns col k (slot A, block base
// t1 = 3(m-k-1)) and col 32+k (slot B, t1 = 3(m-k-33)). Three cells per slot
// per iteration via a running linear sum:
//   c1 = m2 + lg2(S1),           m2 = max(x,y),  S1 = 1 + ex2(-|x-y|)
//   c2 = m3 + lg2(S2),  m3 = max(m2+b1, z2), S2 = ex2(m2+b1-m3)S1 + ex2(z2-m3)
//   c3 = m4 + lg2(S3),  m4 = max(m3+b2, z3), S3 = ex2(m3+b2-m4)S2 + ex2(z3-m4)
// Indices clamped (frozen) at each slot's first/last valid block; clamped-in
// garbage is confined to the virtual t>=200 diagonal and never captured.
// ---------------------------------------------------------------------------
__global__ void __launch_bounds__(256)
rnnt_dp_kernel(const int* __restrict__ input_lens,
               const int* __restrict__ target_lens,
               float* __restrict__ out) {
    extern __shared__ float sm[];

    int b = blockIdx.x;
    int tid = threadIdx.x;

    {   // flat stage, 16B
        const float4* src = (const float4*)(g_pad + b * PADSZ);
        float4* dst = (float4*)sm;
#pragma unroll 4
        for (int i = tid; i < PADSZ / 4; i += 256) dst[i] = src[i];
    }
    __syncthreads();
    if (tid >= 32) return;

    int ti = input_lens[b] - 1;     // >= 99
    int ui = target_lens[b] - 1;    // >= 24

    int k = tid;
    int srcLane = (k + 31) & 31;
    bool actBrow = (k <= 17);

    const float* rbA = sm + k * RW;                                // blank col k
    const float* reA = (k > 0) ? sm + E0 + (k - 1) * RW : sm + D0; // emit col k-1
    const float* rbB = actBrow ? sm + (32 + k) * RW : sm + D0;     // blank col 32+k
    const float* reB = actBrow ? sm + E0 + (31 + k) * RW : sm + D0;// emit col 31+k

    // operand bases: element for (idx, i) is p[idx + i]
    const float* pAb = rbA + (FRONT - 3 * k - 4);   // blank[k][t1+i-1]
    const float* pAe = reA + (FRONT - 3 * k - 3);   // emit[k-1][t1+i]
    const float* pBb = rbB + (FRONT - 3 * k - 100); // blank[32+k][t1B+i-1]
    const float* pBe = reB + (FRONT - 3 * k - 99);  // emit[31+k][t1B+i]

    // index clamps: A in [3, 3k+201] (FRONT covers low), B in [3k+99, 3k+297]
    int capA = 3 * k + 201;
    int loB  = 3 * k + 99, capB = 3 * k + 297;

    // capture: r = ti % 3 selects c_{r+1} at block m
    int r  = ti - (ti / 3) * 3;
    int t1cap = ti - r;
    bool r0 = (r == 0), r1 = (r == 1);
    int mA = (k == ui)        ? t1cap / 3 + k + 1  : -1;
    int mB = ((32 + k) == ui) ? t1cap / 3 + k + 33 : -1;

    float own0 = (k == 0) ? 0.0f : SENT;   // lane 0: seed (pairs with poked cell)
    float own1 = SENT;
    float e1A = SENT, e2A = SENT, e3A = SENT;
    float e1B = SENT, e2B = SENT, e3B = SENT;
    float fin = 0.0f;
    bool is31 = (k == 31);

#pragma unroll 4
    for (int m = 1; m <= MITER; ++m) {
        float n1A = __shfl_sync(0xffffffffu, e1A, srcLane);
        float n2A = __shfl_sync(0xffffffffu, e2A, srcLane);
        float n3A = __shfl_sync(0xffffffffu, e3A, srcLane);
        float n1B = __shfl_sync(0xffffffffu, e1B, srcLane);
        float n2B = __shfl_sync(0xffffffffu, e2B, srcLane);
        float n3B = __shfl_sync(0xffffffffu, e3B, srcLane);

        int idx  = 3 * m;
        int idxA = min(idx, capA);
        int idxB = min(max(idx, loB), capB);

        float bA0 = pAb[idxA], bA1 = pAb[idxA + 1], bA2 = pAb[idxA + 2];
        float gA0 = pAe[idxA], gA1 = pAe[idxA + 1], gA2 = pAe[idxA + 2];
        float bB0 = pBb[idxB], bB1 = pBb[idxB + 1], bB2 = pBb[idxB + 2];
        float gB0 = pBe[idxB], gB1 = pBe[idxB + 1], gB2 = pBe[idxB + 2];

        // ---- slot A ----
        float xA  = own0 + bA0;
        float yA  = n1A + gA0;
        float m2A = fmaxf(xA, yA);
        float S1A = 1.0f + ex2f(-fabsf(xA - yA));
        float c1A = m2A + lg2f(S1A);
        float uA  = m2A + bA1;
        float z2A = n2A + gA1;
        float m3A = fmaxf(uA, z2A);
        float S2A = ex2f(uA - m3A) * S1A + ex2f(z2A - m3A);
        float c2A = m3A + lg2f(S2A);
        float vA  = m3A + bA2;
        float z3A = n3A + gA2;
        float m4A = fmaxf(vA, z3A);
        float S3A = ex2f(vA - m4A) * S2A + ex2f(z3A - m4A);
        float c3A = m4A + lg2f(S3A);

        // ---- slot B ----
        float xB  = own1 + bB0;
        float yB  = n1B + gB0;
        float m2B = fmaxf(xB, yB);
        float S1B = 1.0f + ex2f(-fabsf(xB - yB));
        float c1B = m2B + lg2f(S1B);
        float uB  = m2B + bB1;
        float z2B = n2B + gB1;
        float m3B = fmaxf(uB, z2B);
        float S2B = ex2f(uB - m3B) * S1B + ex2f(z2B - m3B);
        float c2B = m3B + lg2f(S2B);
        float vB  = m3B + bB2;
        float z3B = n3B + gB2;
        float m4B = fmaxf(vB, z3B);
        float S3B = ex2f(vB - m4B) * S2B + ex2f(z3B - m4B);
        float c3B = m4B + lg2f(S3B);

        if (m == mA) fin = r0 ? c1A : (r1 ? c2A : c3A);
        if (m == mB) fin = r0 ? c1B : (r1 ? c2B : c3B);

        own0 = c3A;
        own1 = c3B;
        e1A = c1A; e2A = c2A; e3A = c3A;
        e1B = is31 ? c1A : c1B;          // lane 31 mirrors col 31 (A) into the B
        e2B = is31 ? c2A : c2B;          // channel -> lane 0's col-32 neighbor
        e3B = is31 ? c3A : c3B;
    }

    if (mA >= 0 || mB >= 0) {
        float loss2 = fin + sm[ui * RW + FRONT + ti];   // + blank2[b][ti][ui]
        atomicAdd(out, -loss2 * LN2 * (1.0f / BB));
    }
}

// ---------------------------------------------------------------------------
extern "C" void kernel_launch(void* const* d_in, const int* in_sizes, int n_in,
                              void* d_out, int out_size) {
    const float* h           = (const float*)d_in[0];
    const int*   targets     = (const int*)d_in[1];
    const int*   input_lens  = (const int*)d_in[2];
    const int*   target_lens = (const int*)d_in[3];
    float* out = (float*)d_out;

    size_t smem = (size_t)PADSZ * sizeof(float);   // 120,000 B
    cudaFuncSetAttribute(rnnt_dp_kernel,
                         cudaFuncAttributeMaxDynamicSharedMemorySize, (int)smem);

    lse_gather_kernel<<<BB * UU, 64>>>(h, targets, out);
    rnnt_dp_kernel<<<BB, 256, smem>>>(input_lens, target_lens, out);
}